// round 9
// baseline (speedup 1.0000x reference)
#include <cuda_runtime.h>
#include <cstdint>

// ---------------------------------------------------------------------------
// QuadConv via baseline-PTX tf32 mma.sync + ldmatrix (virtual arch compute_103).
//
//   out[N,128] = concat_k( F[idx[:,k]] ) @ W^T + b
//   N=262144, C_IN=C_OUT=128, K=9 -> GEMM M=N, N=128, K=1152 (A row-gathered).
//   neigh_idx is int32 on the wire.
//
// R8: de-serialize the k-block phases.
//  - 3-stage cp.async pipeline, ONE __syncthreads per k-block
//  - loads issued AFTER the barrier, interleaved between mma s-steps
//    (volatile-asm order keeps them in HMMA shadow)
//  - indices read straight from global (L1-resident), freeing smem for stage 3
//  - A raw fp32 in smem; RNA->tf32 via +0x1000 on fragments (R7, bit-exact)
// ---------------------------------------------------------------------------

namespace qc {
constexpr int NPTS   = 262144;
constexpr int CIN    = 128;
constexpr int COUT   = 128;
constexpr int KNB    = 9;
constexpr int KTOT   = KNB * CIN;      // 1152
constexpr int NKB    = KTOT / 32;      // 36 k-blocks of 32
constexpr int MTILE  = 128;
constexpr int CTAS   = NPTS / MTILE;   // 2048
constexpr int THREADS = 256;

constexpr int ROWPAD = 36;             // 36 mod 32 = 4 -> conflict-free ldmatrix
constexpr int A_FLOATS = MTILE * ROWPAD;   // 4608
constexpr int B_FLOATS = COUT * ROWPAD;    // 4608
constexpr int STAGE_FLOATS = A_FLOATS + B_FLOATS;   // 9216
constexpr int NSTAGE = 3;
constexpr int OFF_BIAS = NSTAGE * STAGE_FLOATS;     // 27648
constexpr int SMEM_FLOATS = OFF_BIAS + COUT;        // 27776
constexpr int SMEM_BYTES  = SMEM_FLOATS * 4;        // 111,104 -> 2 CTAs/SM
} // namespace qc

// W pre-converted to tf32 (RNA) once per launch. Static device scratch.
__device__ uint32_t W_TF32[qc::COUT * qc::KTOT];

// ------------------------------ PTX helpers -------------------------------

__device__ __forceinline__ uint32_t smem_u32(const void* p) {
    return (uint32_t)__cvta_generic_to_shared(p);
}

__device__ __forceinline__ void cp_async16(uint32_t dst, const void* src, int src_size) {
    asm volatile("cp.async.cg.shared.global [%0], [%1], 16, %2;"
                 ::"r"(dst), "l"(src), "r"(src_size) : "memory");
}
__device__ __forceinline__ void cp_commit() {
    asm volatile("cp.async.commit_group;" ::: "memory");
}
template <int N>
__device__ __forceinline__ void cp_wait() {
    asm volatile("cp.async.wait_group %0;" ::"n"(N) : "memory");
}

__device__ __forceinline__ uint32_t f2tf32(float f) {
    uint32_t u;
    asm("cvt.rna.tf32.f32 %0, %1;" : "=r"(u) : "f"(f));
    return u;
}

__device__ __forceinline__ void ldmatrix_x4(uint32_t& r0, uint32_t& r1,
                                            uint32_t& r2, uint32_t& r3, uint32_t addr) {
    asm volatile("ldmatrix.sync.aligned.m8n8.x4.shared.b16 {%0,%1,%2,%3}, [%4];"
                 : "=r"(r0), "=r"(r1), "=r"(r2), "=r"(r3) : "r"(addr));
}

__device__ __forceinline__ void mma_tf32(float& c0, float& c1, float& c2, float& c3,
                                         uint32_t a0, uint32_t a1, uint32_t a2, uint32_t a3,
                                         uint32_t b0, uint32_t b1) {
    asm volatile(
        "mma.sync.aligned.m16n8k8.row.col.f32.tf32.tf32.f32 "
        "{%0,%1,%2,%3}, {%4,%5,%6,%7}, {%8,%9}, {%0,%1,%2,%3};"
        : "+f"(c0), "+f"(c1), "+f"(c2), "+f"(c3)
        : "r"(a0), "r"(a1), "r"(a2), "r"(a3), "r"(b0), "r"(b1));
}

// ----------------------- pre-kernel: W -> tf32 -----------------------------

__global__ void wconv_kernel(const float* __restrict__ W) {
    int i = blockIdx.x * 256 + threadIdx.x;
    if (i < qc::COUT * qc::KTOT) W_TF32[i] = f2tf32(W[i]);
}

// ------------------------------- kernel -----------------------------------

__global__ void __launch_bounds__(qc::THREADS, 2)
quadconv_mma_kernel(const float* __restrict__ F,
                    const int* __restrict__ NIDX,
                    const float* __restrict__ BIAS,
                    float* __restrict__ OUT) {
    using namespace qc;
    extern __shared__ float sm[];
    float* sbias = sm + OFF_BIAS;

    const uint32_t sm_u = smem_u32(sm);

    const int tid  = threadIdx.x;
    const int wid  = tid >> 5;    // 0..7
    const int lane = tid & 31;
    const int g    = lane >> 2;
    const int klo  = lane & 3;
    const int gb   = blockIdx.x * MTILE;

    if (tid < COUT) sbias[tid] = BIAS[tid];

    // per-thread loader coordinates: 4 chunks, rows tid>>3 + 32*i, seg tid&7
    const int lrow = tid >> 3;
    const int lseg = tid & 7;

    // A loader: gather rows for k-block kb into stage st (raw fp32, zfill OOB)
    auto load_A = [&](int kb, int st) {
        const int kn   = kb >> 2;
        const int coff = (kb & 3) * 32;
        const uint32_t dst0 = sm_u + (uint32_t)(st * STAGE_FLOATS) * 4;
#pragma unroll
        for (int i = 0; i < 4; i++) {
            int row = lrow + i * 32;
            int nb  = NIDX[(size_t)(gb + row) * KNB + kn];
            bool ok = (unsigned)nb < (unsigned)NPTS;
            const float* src = F + (size_t)(ok ? nb : 0) * CIN + coff + lseg * 4;
            cp_async16(dst0 + (uint32_t)(row * ROWPAD + lseg * 4) * 4, src, ok ? 16 : 0);
        }
    };
    // B loader: W chunk (already tf32) for k-block kb into stage st
    auto load_B = [&](int kb, int st) {
        const uint32_t dst0 = sm_u + (uint32_t)(st * STAGE_FLOATS + A_FLOATS) * 4;
#pragma unroll
        for (int i = 0; i < 4; i++) {
            int n = lrow + i * 32;
            const uint32_t* src = W_TF32 + (size_t)n * KTOT + kb * 32 + lseg * 4;
            cp_async16(dst0 + (uint32_t)(n * ROWPAD + lseg * 4) * 4, src, 16);
        }
    };

    // ---- warp tiling: 8 warps 2x4, warp tile 64(M) x 32(N) -----------------
    const int Mbase = (wid >> 2) * 64;
    const int Nbase = (wid & 3) * 32;
    float acc[4][4][4];
#pragma unroll
    for (int mf = 0; mf < 4; mf++)
#pragma unroll
        for (int nf = 0; nf < 4; nf++)
#pragma unroll
            for (int q = 0; q < 4; q++) acc[mf][nf][q] = 0.f;

    // ---- ldmatrix per-lane base offsets (floats) ----------------------------
    const int a_rit = (lane & 7) + ((lane >> 3) & 1) * 8;
    const int a_k4  = (lane >> 4) * 4;
    uint32_t aoff[4];
#pragma unroll
    for (int mf = 0; mf < 4; mf++)
        aoff[mf] = (uint32_t)(((Mbase + mf * 16 + a_rit) * ROWPAD + a_k4) * 4);
    const int b_nr = ((lane >> 4) & 1) * 8 + (lane & 7);
    const int b_k4 = ((lane >> 3) & 1) * 4;
    uint32_t boff[2];
#pragma unroll
    for (int p = 0; p < 2; p++)
        boff[p] = (uint32_t)(((Nbase + p * 16 + b_nr) * ROWPAD + b_k4) * 4 +
                             A_FLOATS * 4);

    // one s-step (k=8): ldmatrix A/B, RNA fixup on A, 16 HMMA
    auto mma_step = [&](uint32_t stg_u, int s) {
        uint32_t afr[4][4];
#pragma unroll
        for (int mf = 0; mf < 4; mf++)
            ldmatrix_x4(afr[mf][0], afr[mf][1], afr[mf][2], afr[mf][3],
                        stg_u + aoff[mf] + s * 32);
        uint32_t bfr[4][2];
#pragma unroll
        for (int p = 0; p < 2; p++)
            ldmatrix_x4(bfr[2 * p][0], bfr[2 * p][1],
                        bfr[2 * p + 1][0], bfr[2 * p + 1][1],
                        stg_u + boff[p] + s * 32);
#pragma unroll
        for (int mf = 0; mf < 4; mf++) {
            afr[mf][0] += 0x1000u; afr[mf][1] += 0x1000u;
            afr[mf][2] += 0x1000u; afr[mf][3] += 0x1000u;
        }
#pragma unroll
        for (int mf = 0; mf < 4; mf++)
#pragma unroll
            for (int nf = 0; nf < 4; nf++)
                mma_tf32(acc[mf][nf][0], acc[mf][nf][1],
                         acc[mf][nf][2], acc[mf][nf][3],
                         afr[mf][0], afr[mf][1], afr[mf][2], afr[mf][3],
                         bfr[nf][0], bfr[nf][1]);
    };

    // ---- prologue: prefetch k-blocks 0 and 1 (groups G-2, G-1) --------------
    load_A(0, 0); load_B(0, 0); cp_commit();
    load_A(1, 1); load_B(1, 1); cp_commit();

    // ---- main K loop: 1 barrier per kb; loads hidden between s-steps --------
    // group ledger: iter kb commits exactly one group (maybe empty); before
    // the wait at iter kb the two newest groups hold tiles kb+1, kb+2(-ish),
    // so wait<1> completes the group holding tiles kb.
    for (int kb = 0; kb < NKB; kb++) {
        const int st = kb % 3;
        const uint32_t stg_u = sm_u + (uint32_t)(st * STAGE_FLOATS) * 4;

        cp_wait<1>();
        __syncthreads();   // orders mma(kb-1) reads before load(kb+2) writes

        const int  pf    = kb + 2;
        const bool do_pf = pf < NKB;
        const int  pst   = (kb + 2) % 3;

        mma_step(stg_u, 0);
        if (do_pf) load_A(pf, pst);
        mma_step(stg_u, 1);
        if (do_pf) load_B(pf, pst);
        mma_step(stg_u, 2);
        cp_commit();
        mma_step(stg_u, 3);
    }

    // ---- epilogue: add bias, float2 stores ----------------------------------
#pragma unroll
    for (int mf = 0; mf < 4; mf++) {
#pragma unroll
        for (int nf = 0; nf < 4; nf++) {
            int col  = Nbase + nf * 8 + 2 * klo;
            float bx = sbias[col], by = sbias[col + 1];
            size_t r0 = (size_t)(gb + Mbase + mf * 16 + g) * COUT + col;
            size_t r1 = r0 + (size_t)8 * COUT;
            float2 v0 = make_float2(acc[mf][nf][0] + bx, acc[mf][nf][1] + by);
            float2 v1 = make_float2(acc[mf][nf][2] + bx, acc[mf][nf][3] + by);
            *(float2*)(OUT + r0) = v0;
            *(float2*)(OUT + r1) = v1;
        }
    }
}

// ----------------------------- launch glue --------------------------------

extern "C" void kernel_launch(void* const* d_in, const int* in_sizes, int n_in,
                              void* d_out, int out_size) {
    using namespace qc;
    const float* F = (const float*)d_in[0];
    const int*   I = (const int*)d_in[1];
    const float* W = (const float*)d_in[2];
    const float* B = (const float*)d_in[3];
    for (int i = 0; i < n_in; i++) {
        switch (in_sizes[i]) {
            case NPTS * CIN:       F = (const float*)d_in[i]; break;      // 33554432
            case NPTS * KNB:       I = (const int*)d_in[i];   break;      // 2359296
            case COUT * KNB * CIN: W = (const float*)d_in[i]; break;      // 147456
            case COUT:             B = (const float*)d_in[i]; break;      // 128
            default: break;
        }
    }
    wconv_kernel<<<(COUT * KTOT + 255) / 256, 256>>>(W);
    cudaFuncSetAttribute(quadconv_mma_kernel,
                         cudaFuncAttributeMaxDynamicSharedMemorySize, SMEM_BYTES);
    quadconv_mma_kernel<<<CTAS, THREADS, SMEM_BYTES>>>(F, I, B, (float*)d_out);
}

// round 10
// speedup vs baseline: 1.4038x; 1.4038x over previous
#include <cuda_runtime.h>
#include <cstdint>

// ---------------------------------------------------------------------------
// QuadConv via baseline-PTX tf32 mma.sync + ldmatrix (virtual arch compute_103).
//
//   out[N,128] = concat_k( F[idx[:,k]] ) @ W^T + b
//   N=262144, C_IN=C_OUT=128, K=9 -> GEMM M=N, N=128, K=1152 (A row-gathered).
//   neigh_idx is int32 on the wire.
//
// R9: L1-crossbar diet via warp-tile enlargement. R7 measurements showed LDS
// traffic (132KB/CTA-kb) co-saturated with tensor (2048 cyc) -> tensor pinned
// ~56%. Now 4 warps in 2x2 grid, warp tile 64x64: A fragment redundancy 4->2,
// ldmatrix traffic 96->64KB/CTA-kb, L1 ~1600 cyc < tensor 2048 cyc.
// Loop structure reverted to R7 (R8's interleaved loads regressed).
// A raw fp32 in smem; RNA->tf32 via +0x1000 on fragments (bit-exact).
// ---------------------------------------------------------------------------

namespace qc {
constexpr int NPTS   = 262144;
constexpr int CIN    = 128;
constexpr int COUT   = 128;
constexpr int KNB    = 9;
constexpr int KTOT   = KNB * CIN;      // 1152
constexpr int NKB    = KTOT / 32;      // 36 k-blocks of 32
constexpr int MTILE  = 128;
constexpr int CTAS   = NPTS / MTILE;   // 2048
constexpr int THREADS = 128;           // 4 warps

constexpr int ROWPAD = 36;             // 32 + 4 pad; conflict-free ldmatrix
constexpr int A_FLOATS   = MTILE * ROWPAD;      // 4608 per buffer
constexpr int B_FLOATS   = COUT * ROWPAD;       // 4608 per buffer
constexpr int OFF_A      = 0;                   // 2 buffers
constexpr int OFF_B      = 2 * A_FLOATS;        // 2 buffers
constexpr int OFF_IDX    = OFF_B + 2 * B_FLOATS;
constexpr int OFF_BIAS   = OFF_IDX + KNB * MTILE;
constexpr int SMEM_FLOATS = OFF_BIAS + COUT;
constexpr int SMEM_BYTES  = SMEM_FLOATS * 4;    // 78,848 -> 2 CTAs/SM
} // namespace qc

// W pre-converted to tf32 (RNA) once per launch. Static device scratch.
__device__ uint32_t W_TF32[qc::COUT * qc::KTOT];

// ------------------------------ PTX helpers -------------------------------

__device__ __forceinline__ uint32_t smem_u32(const void* p) {
    return (uint32_t)__cvta_generic_to_shared(p);
}

__device__ __forceinline__ void cp_async16(uint32_t dst, const void* src, int src_size) {
    asm volatile("cp.async.cg.shared.global [%0], [%1], 16, %2;"
                 ::"r"(dst), "l"(src), "r"(src_size) : "memory");
}
__device__ __forceinline__ void cp_commit() {
    asm volatile("cp.async.commit_group;" ::: "memory");
}
template <int N>
__device__ __forceinline__ void cp_wait() {
    asm volatile("cp.async.wait_group %0;" ::"n"(N) : "memory");
}

__device__ __forceinline__ uint32_t f2tf32(float f) {
    uint32_t u;
    asm("cvt.rna.tf32.f32 %0, %1;" : "=r"(u) : "f"(f));
    return u;
}

__device__ __forceinline__ void ldmatrix_x4(uint32_t& r0, uint32_t& r1,
                                            uint32_t& r2, uint32_t& r3, uint32_t addr) {
    asm volatile("ldmatrix.sync.aligned.m8n8.x4.shared.b16 {%0,%1,%2,%3}, [%4];"
                 : "=r"(r0), "=r"(r1), "=r"(r2), "=r"(r3) : "r"(addr));
}

__device__ __forceinline__ void mma_tf32(float& c0, float& c1, float& c2, float& c3,
                                         uint32_t a0, uint32_t a1, uint32_t a2, uint32_t a3,
                                         uint32_t b0, uint32_t b1) {
    asm volatile(
        "mma.sync.aligned.m16n8k8.row.col.f32.tf32.tf32.f32 "
        "{%0,%1,%2,%3}, {%4,%5,%6,%7}, {%8,%9}, {%0,%1,%2,%3};"
        : "+f"(c0), "+f"(c1), "+f"(c2), "+f"(c3)
        : "r"(a0), "r"(a1), "r"(a2), "r"(a3), "r"(b0), "r"(b1));
}

// ----------------------- pre-kernel: W -> tf32 -----------------------------

__global__ void wconv_kernel(const float* __restrict__ W) {
    int i = blockIdx.x * 256 + threadIdx.x;
    if (i < qc::COUT * qc::KTOT) W_TF32[i] = f2tf32(W[i]);
}

// ------------------------------- kernel -----------------------------------

__global__ void __launch_bounds__(qc::THREADS, 2)
quadconv_mma_kernel(const float* __restrict__ F,
                    const int* __restrict__ NIDX,
                    const float* __restrict__ BIAS,
                    float* __restrict__ OUT) {
    using namespace qc;
    extern __shared__ float sm[];
    float* sA    = sm + OFF_A;                 // [2][128][36] raw fp32 (gathered)
    float* sB    = sm + OFF_B;                 // [2][128][36] tf32 (pre-converted W)
    int*   sidx  = (int*)(sm + OFF_IDX);       // [9][128]
    float* sbias = sm + OFF_BIAS;              // [128]

    const uint32_t sA_u = smem_u32(sA);
    const uint32_t sB_u = smem_u32(sB);

    const int tid  = threadIdx.x;
    const int wid  = tid >> 5;    // 0..3
    const int lane = tid & 31;
    const int g    = lane >> 2;   // 0..7
    const int klo  = lane & 3;    // 0..3
    const int gb   = blockIdx.x * MTILE;

    // ---- stage neighbor indices and bias -----------------------------------
    for (int e = tid; e < KNB * MTILE; e += THREADS) {
        int row = e / KNB, kn = e % KNB;
        sidx[kn * MTILE + row] = NIDX[(size_t)(gb + row) * KNB + kn];
    }
    if (tid < COUT) sbias[tid] = BIAS[tid];
    __syncthreads();

    // ---- tile loader: A gather (zfill OOB, raw fp32) + B (tf32) ------------
    const int lrow = tid >> 3;   // 0..15
    const int lseg = tid & 7;    // 0..7
    auto load_tiles = [&](int kb, int buf) {
        const int kn   = kb >> 2;
        const int coff = (kb & 3) * 32;
        const int* idxp = sidx + kn * MTILE;
#pragma unroll
        for (int i = 0; i < 8; i++) {          // A: 1024 chunks / 128 thr
            int row = lrow + i * 16;
            int nb  = idxp[row];
            bool ok = (unsigned)nb < (unsigned)NPTS;
            const float* src = F + (size_t)(ok ? nb : 0) * CIN + coff + lseg * 4;
            cp_async16(sA_u + (uint32_t)(buf * A_FLOATS + row * ROWPAD + lseg * 4) * 4,
                       src, ok ? 16 : 0);
        }
#pragma unroll
        for (int i = 0; i < 8; i++) {          // B: 1024 chunks / 128 thr
            int n = lrow + i * 16;
            const uint32_t* src = W_TF32 + (size_t)n * KTOT + kb * 32 + lseg * 4;
            cp_async16(sB_u + (uint32_t)(buf * B_FLOATS + n * ROWPAD + lseg * 4) * 4,
                       src, 16);
        }
    };

    // ---- warp tiling: 4 warps 2x2, warp tile 64(M) x 64(N) -----------------
    const int Mbase = (wid >> 1) * 64;
    const int Nbase = (wid & 1) * 64;
    float acc[4][8][4];
#pragma unroll
    for (int mf = 0; mf < 4; mf++)
#pragma unroll
        for (int nf = 0; nf < 8; nf++)
#pragma unroll
            for (int q = 0; q < 4; q++) acc[mf][nf][q] = 0.f;

    // ---- ldmatrix per-lane base offsets (bytes, buffer-relative) -----------
    const int a_rit = (lane & 7) + ((lane >> 3) & 1) * 8;
    const int a_k4  = (lane >> 4) * 4;
    uint32_t aoff[4];
#pragma unroll
    for (int mf = 0; mf < 4; mf++)
        aoff[mf] = (uint32_t)(((Mbase + mf * 16 + a_rit) * ROWPAD + a_k4) * 4);
    const int b_nr = ((lane >> 4) & 1) * 8 + (lane & 7);
    const int b_k4 = ((lane >> 3) & 1) * 4;
    uint32_t boff[4];
#pragma unroll
    for (int p = 0; p < 4; p++)
        boff[p] = (uint32_t)(((Nbase + p * 16 + b_nr) * ROWPAD + b_k4) * 4);

    // ---- prologue -----------------------------------------------------------
    load_tiles(0, 0);
    cp_commit();

    // ---- main K loop (R7 structure: loads first, then wait, then mma) ------
    for (int kb = 0; kb < NKB; kb++) {
        const int buf = kb & 1;
        if (kb + 1 < NKB) {
            load_tiles(kb + 1, buf ^ 1);
            cp_commit();
            cp_wait<1>();
        } else {
            cp_wait<0>();
        }
        __syncthreads();   // cross-thread visibility of buf's tiles

        const uint32_t abuf = sA_u + (uint32_t)(buf * A_FLOATS) * 4;
        const uint32_t bbuf = sB_u + (uint32_t)(buf * B_FLOATS) * 4;

#pragma unroll
        for (int s = 0; s < 4; s++) {          // 4 k-steps of 8
            uint32_t afr[4][4];
#pragma unroll
            for (int mf = 0; mf < 4; mf++)
                ldmatrix_x4(afr[mf][0], afr[mf][1], afr[mf][2], afr[mf][3],
                            abuf + aoff[mf] + s * 32);
            uint32_t bfr[8][2];
#pragma unroll
            for (int p = 0; p < 4; p++)
                ldmatrix_x4(bfr[2 * p][0], bfr[2 * p][1],
                            bfr[2 * p + 1][0], bfr[2 * p + 1][1],
                            bbuf + boff[p] + s * 32);
            // RNA-to-tf32 on raw fp32 A fragments (+0x1000; HW drops low 13b)
#pragma unroll
            for (int mf = 0; mf < 4; mf++) {
                afr[mf][0] += 0x1000u; afr[mf][1] += 0x1000u;
                afr[mf][2] += 0x1000u; afr[mf][3] += 0x1000u;
            }
#pragma unroll
            for (int mf = 0; mf < 4; mf++)
#pragma unroll
                for (int nf = 0; nf < 8; nf++)
                    mma_tf32(acc[mf][nf][0], acc[mf][nf][1],
                             acc[mf][nf][2], acc[mf][nf][3],
                             afr[mf][0], afr[mf][1], afr[mf][2], afr[mf][3],
                             bfr[nf][0], bfr[nf][1]);
        }
        __syncthreads();   // all reads of buf done before kb+2 overwrites it
    }

    // ---- epilogue: add bias, float2 stores ----------------------------------
#pragma unroll
    for (int mf = 0; mf < 4; mf++) {
#pragma unroll
        for (int nf = 0; nf < 8; nf++) {
            int col  = Nbase + nf * 8 + 2 * klo;
            float bx = sbias[col], by = sbias[col + 1];
            size_t r0 = (size_t)(gb + Mbase + mf * 16 + g) * COUT + col;
            size_t r1 = r0 + (size_t)8 * COUT;
            float2 v0 = make_float2(acc[mf][nf][0] + bx, acc[mf][nf][1] + by);
            float2 v1 = make_float2(acc[mf][nf][2] + bx, acc[mf][nf][3] + by);
            *(float2*)(OUT + r0) = v0;
            *(float2*)(OUT + r1) = v1;
        }
    }
}

// ----------------------------- launch glue --------------------------------

extern "C" void kernel_launch(void* const* d_in, const int* in_sizes, int n_in,
                              void* d_out, int out_size) {
    using namespace qc;
    const float* F = (const float*)d_in[0];
    const int*   I = (const int*)d_in[1];
    const float* W = (const float*)d_in[2];
    const float* B = (const float*)d_in[3];
    for (int i = 0; i < n_in; i++) {
        switch (in_sizes[i]) {
            case NPTS * CIN:       F = (const float*)d_in[i]; break;      // 33554432
            case NPTS * KNB:       I = (const int*)d_in[i];   break;      // 2359296
            case COUT * KNB * CIN: W = (const float*)d_in[i]; break;      // 147456
            case COUT:             B = (const float*)d_in[i]; break;      // 128
            default: break;
        }
    }
    wconv_kernel<<<(COUT * KTOT + 255) / 256, 256>>>(W);
    cudaFuncSetAttribute(quadconv_mma_kernel,
                         cudaFuncAttributeMaxDynamicSharedMemorySize, SMEM_BYTES);
    quadconv_mma_kernel<<<CTAS, THREADS, SMEM_BYTES>>>(F, I, B, (float*)d_out);
}

// round 11
// speedup vs baseline: 1.5284x; 1.0888x over previous
#include <cuda_runtime.h>
#include <cstdint>

// ---------------------------------------------------------------------------
// QuadConv via baseline-PTX tf32 mma.sync + ldmatrix (virtual arch compute_103).
//
//   out[N,128] = concat_k( F[idx[:,k]] ) @ W^T + b
//   N=262144, C_IN=C_OUT=128, K=9 -> GEMM M=N, N=128, K=1152 (A row-gathered).
//   neigh_idx is int32 on the wire.
//
// R10: third barrier domain. Model: wall is per-CTA latency-bound critical
// path; tensor absorbs all offered work (57.4% == 2x975/3400). 3 CTAs/SM
// raises offered tensor work to 86% of pipe capacity.
//   - smem diet: no sidx (indices live in 8 regs/thread, refreshed when the
//     neighbor index changes, i.e. every 4th k-block), bias via __ldg.
//     -> 72KB/CTA, 3 CTAs = 216KB <= 228KB.
//   - reg diet: lazy B fragments (ldmatrix per nf-pair inside mma loop),
//     __launch_bounds__(128,3) -> <=170 regs.
//   - A raw fp32 in smem; RNA->tf32 via +0x1000 on fragments (bit-exact).
// ---------------------------------------------------------------------------

namespace qc {
constexpr int NPTS   = 262144;
constexpr int CIN    = 128;
constexpr int COUT   = 128;
constexpr int KNB    = 9;
constexpr int KTOT   = KNB * CIN;      // 1152
constexpr int NKB    = KTOT / 32;      // 36 k-blocks of 32
constexpr int MTILE  = 128;
constexpr int CTAS   = NPTS / MTILE;   // 2048
constexpr int THREADS = 128;           // 4 warps

constexpr int ROWPAD = 36;             // 32 + 4 pad; conflict-free ldmatrix
constexpr int A_FLOATS   = MTILE * ROWPAD;      // 4608 per buffer
constexpr int B_FLOATS   = COUT * ROWPAD;       // 4608 per buffer
constexpr int OFF_A      = 0;                   // 2 buffers
constexpr int OFF_B      = 2 * A_FLOATS;        // 2 buffers
constexpr int SMEM_FLOATS = OFF_B + 2 * B_FLOATS;   // 18432
constexpr int SMEM_BYTES  = SMEM_FLOATS * 4;        // 73,728 -> 3 CTAs/SM
} // namespace qc

// W pre-converted to tf32 (RNA) once per launch. Static device scratch.
__device__ uint32_t W_TF32[qc::COUT * qc::KTOT];

// ------------------------------ PTX helpers -------------------------------

__device__ __forceinline__ uint32_t smem_u32(const void* p) {
    return (uint32_t)__cvta_generic_to_shared(p);
}

__device__ __forceinline__ void cp_async16(uint32_t dst, const void* src, int src_size) {
    asm volatile("cp.async.cg.shared.global [%0], [%1], 16, %2;"
                 ::"r"(dst), "l"(src), "r"(src_size) : "memory");
}
__device__ __forceinline__ void cp_commit() {
    asm volatile("cp.async.commit_group;" ::: "memory");
}
template <int N>
__device__ __forceinline__ void cp_wait() {
    asm volatile("cp.async.wait_group %0;" ::"n"(N) : "memory");
}

__device__ __forceinline__ uint32_t f2tf32(float f) {
    uint32_t u;
    asm("cvt.rna.tf32.f32 %0, %1;" : "=r"(u) : "f"(f));
    return u;
}

__device__ __forceinline__ void ldmatrix_x4(uint32_t& r0, uint32_t& r1,
                                            uint32_t& r2, uint32_t& r3, uint32_t addr) {
    asm volatile("ldmatrix.sync.aligned.m8n8.x4.shared.b16 {%0,%1,%2,%3}, [%4];"
                 : "=r"(r0), "=r"(r1), "=r"(r2), "=r"(r3) : "r"(addr));
}

__device__ __forceinline__ void mma_tf32(float& c0, float& c1, float& c2, float& c3,
                                         uint32_t a0, uint32_t a1, uint32_t a2, uint32_t a3,
                                         uint32_t b0, uint32_t b1) {
    asm volatile(
        "mma.sync.aligned.m16n8k8.row.col.f32.tf32.tf32.f32 "
        "{%0,%1,%2,%3}, {%4,%5,%6,%7}, {%8,%9}, {%0,%1,%2,%3};"
        : "+f"(c0), "+f"(c1), "+f"(c2), "+f"(c3)
        : "r"(a0), "r"(a1), "r"(a2), "r"(a3), "r"(b0), "r"(b1));
}

// ----------------------- pre-kernel: W -> tf32 -----------------------------

__global__ void wconv_kernel(const float* __restrict__ W) {
    int i = blockIdx.x * 256 + threadIdx.x;
    if (i < qc::COUT * qc::KTOT) W_TF32[i] = f2tf32(W[i]);
}

// ------------------------------- kernel -----------------------------------

__global__ void __launch_bounds__(qc::THREADS, 3)
quadconv_mma_kernel(const float* __restrict__ F,
                    const int* __restrict__ NIDX,
                    const float* __restrict__ BIAS,
                    float* __restrict__ OUT) {
    using namespace qc;
    extern __shared__ float sm[];
    const uint32_t sA_u = smem_u32(sm + OFF_A);
    const uint32_t sB_u = smem_u32(sm + OFF_B);

    const int tid  = threadIdx.x;
    const int wid  = tid >> 5;    // 0..3
    const int lane = tid & 31;
    const int g    = lane >> 2;   // 0..7
    const int klo  = lane & 3;    // 0..3
    const int gb   = blockIdx.x * MTILE;

    // ---- per-thread loader coordinates & register-cached indices -----------
    const int lrow = tid >> 3;    // 0..15
    const int lseg = tid & 7;     // 0..7
    int idxr[8];                  // neighbor index for rows lrow+16i, current kn
    auto refresh_idx = [&](int kn) {
#pragma unroll
        for (int i = 0; i < 8; i++)
            idxr[i] = NIDX[(size_t)(gb + lrow + i * 16) * KNB + kn];
    };

    // A gather (zfill OOB, raw fp32) + B (pre-converted tf32 W chunk).
    // caller guarantees idxr matches kb>>2.
    auto load_tiles = [&](int kb, int buf) {
        const int coff = (kb & 3) * 32;
#pragma unroll
        for (int i = 0; i < 8; i++) {          // A: 1024 chunks / 128 thr
            int row = lrow + i * 16;
            int nb  = idxr[i];
            bool ok = (unsigned)nb < (unsigned)NPTS;
            const float* src = F + (size_t)(ok ? nb : 0) * CIN + coff + lseg * 4;
            cp_async16(sA_u + (uint32_t)(buf * A_FLOATS + row * ROWPAD + lseg * 4) * 4,
                       src, ok ? 16 : 0);
        }
#pragma unroll
        for (int i = 0; i < 8; i++) {          // B: 1024 chunks / 128 thr
            int n = lrow + i * 16;
            const uint32_t* src = W_TF32 + (size_t)n * KTOT + kb * 32 + lseg * 4;
            cp_async16(sB_u + (uint32_t)(buf * B_FLOATS + n * ROWPAD + lseg * 4) * 4,
                       src, 16);
        }
    };

    // ---- warp tiling: 4 warps 2x2, warp tile 64(M) x 64(N) -----------------
    const int Mbase = (wid >> 1) * 64;
    const int Nbase = (wid & 1) * 64;
    float acc[4][8][4];
#pragma unroll
    for (int mf = 0; mf < 4; mf++)
#pragma unroll
        for (int nf = 0; nf < 8; nf++)
#pragma unroll
            for (int q = 0; q < 4; q++) acc[mf][nf][q] = 0.f;

    // ---- ldmatrix per-lane base offsets (bytes, buffer-relative) -----------
    const int a_rit = (lane & 7) + ((lane >> 3) & 1) * 8;
    const int a_k4  = (lane >> 4) * 4;
    uint32_t aoff[4];
#pragma unroll
    for (int mf = 0; mf < 4; mf++)
        aoff[mf] = (uint32_t)(((Mbase + mf * 16 + a_rit) * ROWPAD + a_k4) * 4);
    const int b_nr = ((lane >> 4) & 1) * 8 + (lane & 7);
    const int b_k4 = ((lane >> 3) & 1) * 4;
    uint32_t boff[4];
#pragma unroll
    for (int p = 0; p < 4; p++)
        boff[p] = (uint32_t)(((Nbase + p * 16 + b_nr) * ROWPAD + b_k4) * 4);

    // ---- prologue -----------------------------------------------------------
    refresh_idx(0);
    int kn_cur = 0;
    load_tiles(0, 0);
    cp_commit();

    // ---- main K loop (loads first, then wait, then mma) ---------------------
    for (int kb = 0; kb < NKB; kb++) {
        const int buf = kb & 1;
        const int pf  = kb + 1;
        if (pf < NKB) {
            const int knp = pf >> 2;
            if (knp != kn_cur) { kn_cur = knp; refresh_idx(knp); }
            load_tiles(pf, buf ^ 1);
            cp_commit();
            cp_wait<1>();
        } else {
            cp_wait<0>();
        }
        __syncthreads();   // cross-thread visibility of buf's tiles

        const uint32_t abuf = sA_u + (uint32_t)(buf * A_FLOATS) * 4;
        const uint32_t bbuf = sB_u + (uint32_t)(buf * B_FLOATS) * 4;

#pragma unroll
        for (int s = 0; s < 4; s++) {          // 4 k-steps of 8
            uint32_t afr[4][4];
#pragma unroll
            for (int mf = 0; mf < 4; mf++)
                ldmatrix_x4(afr[mf][0], afr[mf][1], afr[mf][2], afr[mf][3],
                            abuf + aoff[mf] + s * 32);
            // RNA-to-tf32 on raw fp32 A fragments (+0x1000; HW drops low 13b)
#pragma unroll
            for (int mf = 0; mf < 4; mf++) {
                afr[mf][0] += 0x1000u; afr[mf][1] += 0x1000u;
                afr[mf][2] += 0x1000u; afr[mf][3] += 0x1000u;
            }
            // lazy B: one ldmatrix per nf-pair, immediately consumed
#pragma unroll
            for (int p = 0; p < 4; p++) {
                uint32_t b0a, b0b, b1a, b1b;
                ldmatrix_x4(b0a, b0b, b1a, b1b, bbuf + boff[p] + s * 32);
#pragma unroll
                for (int mf = 0; mf < 4; mf++) {
                    mma_tf32(acc[mf][2 * p][0], acc[mf][2 * p][1],
                             acc[mf][2 * p][2], acc[mf][2 * p][3],
                             afr[mf][0], afr[mf][1], afr[mf][2], afr[mf][3],
                             b0a, b0b);
                    mma_tf32(acc[mf][2 * p + 1][0], acc[mf][2 * p + 1][1],
                             acc[mf][2 * p + 1][2], acc[mf][2 * p + 1][3],
                             afr[mf][0], afr[mf][1], afr[mf][2], afr[mf][3],
                             b1a, b1b);
                }
            }
        }
        __syncthreads();   // all reads of buf done before kb+2 overwrites it
    }

    // ---- epilogue: add bias (global, L2-hot), float2 stores -----------------
#pragma unroll
    for (int mf = 0; mf < 4; mf++) {
#pragma unroll
        for (int nf = 0; nf < 8; nf++) {
            int col  = Nbase + nf * 8 + 2 * klo;
            float bx = __ldg(BIAS + col), by = __ldg(BIAS + col + 1);
            size_t r0 = (size_t)(gb + Mbase + mf * 16 + g) * COUT + col;
            size_t r1 = r0 + (size_t)8 * COUT;
            float2 v0 = make_float2(acc[mf][nf][0] + bx, acc[mf][nf][1] + by);
            float2 v1 = make_float2(acc[mf][nf][2] + bx, acc[mf][nf][3] + by);
            *(float2*)(OUT + r0) = v0;
            *(float2*)(OUT + r1) = v1;
        }
    }
}

// ----------------------------- launch glue --------------------------------

extern "C" void kernel_launch(void* const* d_in, const int* in_sizes, int n_in,
                              void* d_out, int out_size) {
    using namespace qc;
    const float* F = (const float*)d_in[0];
    const int*   I = (const int*)d_in[1];
    const float* W = (const float*)d_in[2];
    const float* B = (const float*)d_in[3];
    for (int i = 0; i < n_in; i++) {
        switch (in_sizes[i]) {
            case NPTS * CIN:       F = (const float*)d_in[i]; break;      // 33554432
            case NPTS * KNB:       I = (const int*)d_in[i];   break;      // 2359296
            case COUT * KNB * CIN: W = (const float*)d_in[i]; break;      // 147456
            case COUT:             B = (const float*)d_in[i]; break;      // 128
            default: break;
        }
    }
    wconv_kernel<<<(COUT * KTOT + 255) / 256, 256>>>(W);
    cudaFuncSetAttribute(quadconv_mma_kernel,
                         cudaFuncAttributeMaxDynamicSharedMemorySize, SMEM_BYTES);
    quadconv_mma_kernel<<<CTAS, THREADS, SMEM_BYTES>>>(F, I, B, (float*)d_out);
}